// round 8
// baseline (speedup 1.0000x reference)
#include <cuda_runtime.h>

// Problem constants (fixed shapes: B=1, C=1, H=W=96)
#define NN       9216
#define WW       96
#define INV_SXY  (1.0f / 15.0f)
#define SRGB_SCL 8.0f
#define LOG2E    1.4426950408889634f
#define NHL2E    (-0.7213475204444817f)   // -0.5 * log2(e)

// 48x48 grid of 192x192 tiles -> 1176 tile-pairs; each split into 2 j-row
// blocks (one image row each, so dy is constant per block/u). 2352 blocks.
#define NB      48
#define TILE    192            // NN / NB
#define NPAIR   (TILE / 2)     // 96 j-pairs per tile
#define JROW    48             // j-pairs per block = one 96-px image row
#define TPB     64
#define IPT     3              // TPB * IPT == TILE
#define NTPAIRS (NB * (NB + 1) / 2)   // 1176
#define NBLOCKS (NTPAIRS * 2)         // 2352

// ---- f32x2 helpers (sm_103a packed fp32 pipe; ptxas won't auto-fuse) ----
typedef unsigned long long u64;
__device__ __forceinline__ u64 pack2(float lo, float hi) {
    u64 r; asm("mov.b64 %0, {%1,%2};" : "=l"(r) : "f"(lo), "f"(hi)); return r;
}
__device__ __forceinline__ void unpack2(u64 v, float& lo, float& hi) {
    asm("mov.b64 {%0,%1}, %2;" : "=f"(lo), "=f"(hi) : "l"(v));
}
__device__ __forceinline__ u64 fma2(u64 a, u64 b, u64 c) {
    u64 r; asm("fma.rn.f32x2 %0, %1, %2, %3;" : "=l"(r) : "l"(a), "l"(b), "l"(c)); return r;
}
__device__ __forceinline__ u64 add2(u64 a, u64 b) {
    u64 r; asm("add.rn.f32x2 %0, %1, %2;" : "=l"(r) : "l"(a), "l"(b)); return r;
}
__device__ __forceinline__ unsigned smem_u32(const void* p) {
    unsigned a;
    asm("{ .reg .u64 t; cvta.to.shared.u64 t, %1; cvt.u32.u64 %0, t; }"
        : "=r"(a) : "l"(p));
    return a;
}

// i-side per pixel: {LOG2E*fr, LOG2E*fg, LOG2E*fb, NHL2E*|frgb|^2}, f = 8*rgb
__device__ float4 g_iA[NN];
__device__ float  g_is[NN];
// j-side pair-packed (pair p = pixels 2p,2p+1); 16B = two f32x2 operands:
// p0 = {fr0,fr1 | fg0,fg1}  p1 = {fb0,fb1 | brgb0,brgb1}  p2 = {t0,t1 | s0,s1}
__device__ float4 g_p0[NN / 2];
__device__ float4 g_p1[NN / 2];
__device__ float4 g_p2[NN / 2];

__global__ void precompute_kernel(const float* __restrict__ inp,
                                  const float* __restrict__ img,
                                  float* __restrict__ out, int out_size) {
    int p = blockIdx.x * blockDim.x + threadIdx.x;
    if (p < out_size) out[p] = 0.0f;           // fused output zeroing
    if (p >= NN / 2) return;
    float fr[2], fg[2], fb[2], br[2], tt[2], ss[2];
#pragma unroll
    for (int l = 0; l < 2; l++) {
        int n = 2 * p + l;
        float r = img[n]          * SRGB_SCL;
        float g = img[NN + n]     * SRGB_SCL;
        float b = img[2 * NN + n] * SRGB_SCL;
        float s = inp[n];
        fr[l] = r; fg[l] = g; fb[l] = b;
        br[l] = NHL2E * (r * r + g * g + b * b);
        tt[l] = 1.0f - s; ss[l] = s;
        g_iA[n] = make_float4(LOG2E * r, LOG2E * g, LOG2E * b, br[l]);
        g_is[n] = s;
    }
    g_p0[p] = make_float4(fr[0], fr[1], fg[0], fg[1]);
    g_p1[p] = make_float4(fb[0], fb[1], br[0], br[1]);
    g_p2[p] = make_float4(tt[0], tt[1], ss[0], ss[1]);
}

// w_ij = 2^( a_i + ady + b_j + Frgb_i.Grgb_j + vdx(dx) ) = exp(-0.5*d2)
// Diagonal tile-pairs: acc += w*(1-s_j), then * s_i
// Off-diag tile-pairs: acc += w*(s_i + s_j - 2 s_i s_j)   (covers both orders)
__global__ __launch_bounds__(TPB)
void crf_main_kernel(float* __restrict__ out) {
    __shared__ float2     tab[192];     // tab[idx]={v(idx-95),v(idx-96)}, 8B entries
    __shared__ ulonglong2 sQ0[JROW], sQ1[JROW];
    __shared__ float4     sP2[JROW];
    __shared__ float      sred[TPB / 32];

    // blockIdx -> (tile-pair, j-row-half); decode pair -> (bi, bj), bi <= bj
    int bp   = blockIdx.x >> 1;
    int half = blockIdx.x & 1;
    int bi = 0;
    while (bp >= NB - bi) { bp -= NB - bi; bi++; }
    int bj = bi + bp;

    const int t  = threadIdx.x;
    const int i0 = bi * TILE;
    const int jp = bj * NPAIR + half * JROW;    // j-pair base (one image row)
    const int yj = 2 * bj + half;               // fixed j row

    // j-tile into smem (pair-packed; ulonglong2 halves are f32x2 operands)
    const ulonglong2* __restrict__ gq0 = (const ulonglong2*)g_p0;
    const ulonglong2* __restrict__ gq1 = (const ulonglong2*)g_p1;
    for (int k = t; k < JROW; k += TPB) {
        sQ0[k] = gq0[jp + k];
        sQ1[k] = gq1[jp + k];
        sP2[k] = g_p2[jp + k];
    }
    // spatial dx table: v(d) = -0.5*log2e*(d/15)^2
    for (int idx = t; idx < 191; idx += TPB) {
        float d0 = (float)(idx - 95) * INV_SXY;
        float d1 = (float)(idx - 96) * INV_SXY;
        tab[idx] = make_float2(NHL2E * d0 * d0, NHL2E * d1 * d1);
    }
    const unsigned tbase = smem_u32(tab);

    // per-thread i state
    u64 F2[IPT], F3[IPT], F4[IPT], A2[IPT];
    float si[IPT], acc0[IPT], acc1[IPT];
    unsigned paddr[IPT];
#pragma unroll
    for (int u = 0; u < IPT; u++) {
        int li = u * TPB + t;                   // 0..191 within tile
        int xi = (li >= WW) ? li - WW : li;
        int yi = 2 * bi + (li >= WW);
        float4 A = g_iA[i0 + li];
        float  s = g_is[i0 + li];
        float dy = (float)(yi - yj) * INV_SXY;
        float a  = A.w + NHL2E * dy * dy;       // rgb self + dy term
        F2[u] = pack2(A.x, A.x);
        F3[u] = pack2(A.y, A.y);
        F4[u] = pack2(A.z, A.z);
        A2[u] = pack2(a, a);
        si[u] = s; acc0[u] = 0.0f; acc1[u] = 0.0f;
        paddr[u] = tbase + (unsigned)((xi + 95) * 8);   // jj=0; -16/iter
    }
    __syncthreads();

    if (bi == bj) {
#pragma unroll 2
        for (int jj = 0; jj < JROW; jj++) {
            ulonglong2 Q0 = sQ0[jj], Q1 = sQ1[jj];
            float4 P2 = sP2[jj];
            u64 G2 = Q0.x, G3 = Q0.y, G4 = Q1.x, B2 = Q1.y;
            float t0 = P2.x, t1 = P2.y;
#pragma unroll
            for (int u = 0; u < IPT; u++) {
                u64 axy;
                asm("ld.shared.b64 %0, [%1];" : "=l"(axy) : "r"(paddr[u]));
                u64 arg = add2(A2[u], B2);
                arg = fma2(F2[u], G2, arg);
                arg = fma2(F3[u], G3, arg);
                arg = fma2(F4[u], G4, arg);
                arg = add2(arg, axy);
                float a0, a1, w0, w1;
                unpack2(arg, a0, a1);
                asm("ex2.approx.ftz.f32 %0, %1;" : "=f"(w0) : "f"(a0));
                asm("ex2.approx.ftz.f32 %0, %1;" : "=f"(w1) : "f"(a1));
                acc0[u] = fmaf(w0, t0, acc0[u]);
                acc1[u] = fmaf(w1, t1, acc1[u]);
                paddr[u] -= 16;
            }
        }
    } else {
#pragma unroll 2
        for (int jj = 0; jj < JROW; jj++) {
            ulonglong2 Q0 = sQ0[jj], Q1 = sQ1[jj];
            float4 P2 = sP2[jj];
            u64 G2 = Q0.x, G3 = Q0.y, G4 = Q1.x, B2 = Q1.y;
            float s0 = P2.z, s1 = P2.w;
            float p0 = fmaf(-2.0f, s0, 1.0f);   // 1 - 2*s_j0
            float p1 = fmaf(-2.0f, s1, 1.0f);
#pragma unroll
            for (int u = 0; u < IPT; u++) {
                u64 axy;
                asm("ld.shared.b64 %0, [%1];" : "=l"(axy) : "r"(paddr[u]));
                u64 arg = add2(A2[u], B2);
                arg = fma2(F2[u], G2, arg);
                arg = fma2(F3[u], G3, arg);
                arg = fma2(F4[u], G4, arg);
                arg = add2(arg, axy);
                float a0, a1, w0, w1;
                unpack2(arg, a0, a1);
                asm("ex2.approx.ftz.f32 %0, %1;" : "=f"(w0) : "f"(a0));
                asm("ex2.approx.ftz.f32 %0, %1;" : "=f"(w1) : "f"(a1));
                float c0 = fmaf(si[u], p0, s0);  // s_i + s_j - 2 s_i s_j
                float c1 = fmaf(si[u], p1, s1);
                acc0[u] = fmaf(w0, c0, acc0[u]);
                acc1[u] = fmaf(w1, c1, acc1[u]);
                paddr[u] -= 16;
            }
        }
    }

    float tot = 0.0f;
    if (bi == bj) {
#pragma unroll
        for (int u = 0; u < IPT; u++) tot = fmaf(si[u], acc0[u] + acc1[u], tot);
    } else {
#pragma unroll
        for (int u = 0; u < IPT; u++) tot += acc0[u] + acc1[u];
    }
    tot *= (1.0f / (float)NN);

    // Block reduce: warp shuffle then smem (TPB = 64 -> 2 warps)
#pragma unroll
    for (int off = 16; off > 0; off >>= 1)
        tot += __shfl_xor_sync(0xFFFFFFFFu, tot, off);
    if ((t & 31) == 0) sred[t >> 5] = tot;
    __syncthreads();
    if (t == 0) atomicAdd(out, sred[0] + sred[1]);
}

extern "C" void kernel_launch(void* const* d_in, const int* in_sizes, int n_in,
                              void* d_out, int out_size) {
    const float* inp = (const float*)d_in[0];   // [1,1,96,96] seg probs
    const float* img = (const float*)d_in[1];   // [1,3,96,96] rgb
    float* out = (float*)d_out;

    precompute_kernel<<<(NN / 2 + 255) / 256, 256>>>(inp, img, out, out_size);
    crf_main_kernel<<<NBLOCKS, TPB>>>(out);
}

// round 9
// speedup vs baseline: 1.6000x; 1.6000x over previous
#include <cuda_runtime.h>

// Problem constants (fixed shapes: B=1, C=1, H=W=96)
#define NN       9216
#define WW       96
#define INV_SXY  (1.0f / 15.0f)
#define SRGB_SCL 8.0f
#define LOG2E    1.4426950408889634f
#define NHL2E    (-0.7213475204444817f)   // -0.5 * log2(e)

// 48x48 grid of 192x192 tiles -> 1176 tile-pairs; each split into 2 blocks
// whose j-range is ONE image row (96 px = 48 pairs) so dy is a per-block
// constant folded into the i-side bias. 2352 blocks x 2 warps ~ 32 warps/SM.
#define NB      48
#define TILE    192            // NN / NB
#define NPAIR   (TILE / 2)     // 96 j-pairs per tile
#define JROW    48             // j-pairs per block = one image row
#define TPB     64
#define IPT     3              // TPB * IPT == TILE
#define NTPAIRS (NB * (NB + 1) / 2)   // 1176
#define NBLOCKS (NTPAIRS * 2)         // 2352

// ---- f32x2 helpers (sm_103a packed fp32 pipe; ptxas won't auto-fuse) ----
typedef unsigned long long u64;
__device__ __forceinline__ u64 pack2(float lo, float hi) {
    u64 r; asm("mov.b64 %0, {%1,%2};" : "=l"(r) : "f"(lo), "f"(hi)); return r;
}
__device__ __forceinline__ void unpack2(u64 v, float& lo, float& hi) {
    asm("mov.b64 {%0,%1}, %2;" : "=f"(lo), "=f"(hi) : "l"(v));
}
__device__ __forceinline__ u64 fma2(u64 a, u64 b, u64 c) {
    u64 r; asm("fma.rn.f32x2 %0, %1, %2, %3;" : "=l"(r) : "l"(a), "l"(b), "l"(c)); return r;
}
__device__ __forceinline__ u64 add2(u64 a, u64 b) {
    u64 r; asm("add.rn.f32x2 %0, %1, %2;" : "=l"(r) : "l"(a), "l"(b)); return r;
}

// i-side per pixel: {L2E*fr, L2E*fg, L2E*fb, NHL2E*|frgb|^2}, f = 8*rgb
__device__ float4 g_iA[NN];
__device__ float  g_is[NN];
// j-side pair-packed (pair p = pixels 2p,2p+1); each 16B = two f32x2 operands:
// q0 = {fx0,fx1 | fr0,fr1}   q1 = {fg0,fg1 | fb0,fb1}
// q2 = {bj0,bj1 | t0, t1 }   q3 = {s0, s1  | p0, p1 }   (b=NHL2E*(fx^2+|frgb|^2),
//                                                        t=1-s, p=1-2s)
__device__ float4 g_q0[NN / 2];
__device__ float4 g_q1[NN / 2];
__device__ float4 g_q2[NN / 2];
__device__ float4 g_q3[NN / 2];

__global__ void precompute_kernel(const float* __restrict__ inp,
                                  const float* __restrict__ img,
                                  float* __restrict__ out, int out_size) {
    int p = blockIdx.x * blockDim.x + threadIdx.x;
    if (p < out_size) out[p] = 0.0f;           // fused output zeroing
    if (p >= NN / 2) return;
    float fx[2], fr[2], fg[2], fb[2], bj[2], tt[2], ss[2], pp[2];
#pragma unroll
    for (int l = 0; l < 2; l++) {
        int n = 2 * p + l;
        float x = (float)(n % WW) * INV_SXY;
        float r = img[n]          * SRGB_SCL;
        float g = img[NN + n]     * SRGB_SCL;
        float b = img[2 * NN + n] * SRGB_SCL;
        float s = inp[n];
        fx[l] = x; fr[l] = r; fg[l] = g; fb[l] = b;
        bj[l] = NHL2E * (x * x + r * r + g * g + b * b);
        tt[l] = 1.0f - s; ss[l] = s; pp[l] = fmaf(-2.0f, s, 1.0f);
        g_iA[n] = make_float4(LOG2E * r, LOG2E * g, LOG2E * b,
                              NHL2E * (r * r + g * g + b * b));
        g_is[n] = s;
    }
    g_q0[p] = make_float4(fx[0], fx[1], fr[0], fr[1]);
    g_q1[p] = make_float4(fg[0], fg[1], fb[0], fb[1]);
    g_q2[p] = make_float4(bj[0], bj[1], tt[0], tt[1]);
    g_q3[p] = make_float4(ss[0], ss[1], pp[0], pp[1]);
}

// w_ij = 2^( a_i + b_j + Fx*gx + Fr*gr + Fg*gg + Fb*gb ) = exp(-0.5*d2)
//   a_i includes rgb self-energy + xi^2 + dy^2 terms (dy const per block).
// Diagonal tile-pairs: acc += w*(1-s_j), then * s_i
// Off-diag tile-pairs: acc += w*(s_i + s_j - 2 s_i s_j)  (covers both orders)
// EX2+acc of iteration jj-1 is deferred into iteration jj so MUFU work
// interleaves with the FFMA2 build chain (pipe overlap instead of phase-lock).
__global__ __launch_bounds__(TPB)
void crf_main_kernel(float* __restrict__ out) {
    __shared__ ulonglong2 sQ0[JROW], sQ1[JROW], sQ2[JROW], sQ3[JROW];
    __shared__ float      sred[TPB / 32];

    // blockIdx -> (tile-pair, j-row); decode pair -> (bi, bj), bi <= bj
    int bp   = blockIdx.x >> 1;
    int half = blockIdx.x & 1;
    int bi = 0;
    while (bp >= NB - bi) { bp -= NB - bi; bi++; }
    int bj = bi + bp;

    const int t  = threadIdx.x;
    const int i0 = bi * TILE;
    const int jp = bj * NPAIR + half * JROW;    // j-pair base (one image row)
    const int yj = 2 * bj + half;               // fixed j row

    const ulonglong2* __restrict__ gq0 = (const ulonglong2*)g_q0;
    const ulonglong2* __restrict__ gq1 = (const ulonglong2*)g_q1;
    const ulonglong2* __restrict__ gq2 = (const ulonglong2*)g_q2;
    const ulonglong2* __restrict__ gq3 = (const ulonglong2*)g_q3;
    for (int k = t; k < JROW; k += TPB) {
        sQ0[k] = gq0[jp + k];
        sQ1[k] = gq1[jp + k];
        sQ2[k] = gq2[jp + k];
        sQ3[k] = gq3[jp + k];
    }

    // per-thread i state (broadcast-packed, loop-invariant)
    u64 FX[IPT], FR[IPT], FG[IPT], FB[IPT], A2[IPT];
    float si[IPT], acc0[IPT], acc1[IPT];
#pragma unroll
    for (int u = 0; u < IPT; u++) {
        int li = u * TPB + t;                   // 0..191 within tile
        int xi = (li >= WW) ? li - WW : li;
        int yi = 2 * bi + (li >= WW);
        float4 A = g_iA[i0 + li];
        float  s = g_is[i0 + li];
        float fxi = (float)xi * INV_SXY;
        float dy  = (float)(yi - yj) * INV_SXY;
        float a   = A.w + NHL2E * (fxi * fxi + dy * dy);
        FX[u] = pack2(LOG2E * fxi, LOG2E * fxi);
        FR[u] = pack2(A.x, A.x);
        FG[u] = pack2(A.y, A.y);
        FB[u] = pack2(A.z, A.z);
        A2[u] = pack2(a, a);
        si[u] = s; acc0[u] = 0.0f; acc1[u] = 0.0f;
    }
    __syncthreads();

    u64 warg[IPT];                              // pending args (iter jj-1)
    if (bi == bj) {
        float t0p, t1p;                         // pending coeffs (1-s_j)
        {
            ulonglong2 Q0 = sQ0[0], Q1 = sQ1[0], Q2 = sQ2[0];
            u64 Gx = Q0.x, Gr = Q0.y, Gg = Q1.x, Gb = Q1.y, B2 = Q2.x;
            unpack2(Q2.y, t0p, t1p);
#pragma unroll
            for (int u = 0; u < IPT; u++) {
                u64 arg = add2(A2[u], B2);
                arg = fma2(FX[u], Gx, arg);
                arg = fma2(FR[u], Gr, arg);
                arg = fma2(FG[u], Gg, arg);
                warg[u] = fma2(FB[u], Gb, arg);
            }
        }
#pragma unroll 2
        for (int jj = 1; jj < JROW; jj++) {
            ulonglong2 Q0 = sQ0[jj], Q1 = sQ1[jj], Q2 = sQ2[jj];
            u64 Gx = Q0.x, Gr = Q0.y, Gg = Q1.x, Gb = Q1.y, B2 = Q2.x;
            float t0c, t1c; unpack2(Q2.y, t0c, t1c);
#pragma unroll
            for (int u = 0; u < IPT; u++) {
                float a0, a1, w0, w1;
                unpack2(warg[u], a0, a1);
                asm("ex2.approx.ftz.f32 %0, %1;" : "=f"(w0) : "f"(a0));
                asm("ex2.approx.ftz.f32 %0, %1;" : "=f"(w1) : "f"(a1));
                acc0[u] = fmaf(w0, t0p, acc0[u]);
                acc1[u] = fmaf(w1, t1p, acc1[u]);
                u64 arg = add2(A2[u], B2);
                arg = fma2(FX[u], Gx, arg);
                arg = fma2(FR[u], Gr, arg);
                arg = fma2(FG[u], Gg, arg);
                warg[u] = fma2(FB[u], Gb, arg);
            }
            t0p = t0c; t1p = t1c;
        }
#pragma unroll
        for (int u = 0; u < IPT; u++) {         // retire last iteration
            float a0, a1, w0, w1;
            unpack2(warg[u], a0, a1);
            asm("ex2.approx.ftz.f32 %0, %1;" : "=f"(w0) : "f"(a0));
            asm("ex2.approx.ftz.f32 %0, %1;" : "=f"(w1) : "f"(a1));
            acc0[u] = fmaf(w0, t0p, acc0[u]);
            acc1[u] = fmaf(w1, t1p, acc1[u]);
        }
    } else {
        float s0p, s1p, p0p, p1p;               // pending s_j and 1-2s_j
        {
            ulonglong2 Q0 = sQ0[0], Q1 = sQ1[0], Q2 = sQ2[0], Q3 = sQ3[0];
            u64 Gx = Q0.x, Gr = Q0.y, Gg = Q1.x, Gb = Q1.y, B2 = Q2.x;
            unpack2(Q3.x, s0p, s1p);
            unpack2(Q3.y, p0p, p1p);
#pragma unroll
            for (int u = 0; u < IPT; u++) {
                u64 arg = add2(A2[u], B2);
                arg = fma2(FX[u], Gx, arg);
                arg = fma2(FR[u], Gr, arg);
                arg = fma2(FG[u], Gg, arg);
                warg[u] = fma2(FB[u], Gb, arg);
            }
        }
#pragma unroll 2
        for (int jj = 1; jj < JROW; jj++) {
            ulonglong2 Q0 = sQ0[jj], Q1 = sQ1[jj], Q2 = sQ2[jj], Q3 = sQ3[jj];
            u64 Gx = Q0.x, Gr = Q0.y, Gg = Q1.x, Gb = Q1.y, B2 = Q2.x;
            float s0c, s1c, p0c, p1c;
            unpack2(Q3.x, s0c, s1c);
            unpack2(Q3.y, p0c, p1c);
#pragma unroll
            for (int u = 0; u < IPT; u++) {
                float a0, a1, w0, w1;
                unpack2(warg[u], a0, a1);
                asm("ex2.approx.ftz.f32 %0, %1;" : "=f"(w0) : "f"(a0));
                asm("ex2.approx.ftz.f32 %0, %1;" : "=f"(w1) : "f"(a1));
                float c0 = fmaf(si[u], p0p, s0p);   // s_i + s_j - 2 s_i s_j
                float c1 = fmaf(si[u], p1p, s1p);
                acc0[u] = fmaf(w0, c0, acc0[u]);
                acc1[u] = fmaf(w1, c1, acc1[u]);
                u64 arg = add2(A2[u], B2);
                arg = fma2(FX[u], Gx, arg);
                arg = fma2(FR[u], Gr, arg);
                arg = fma2(FG[u], Gg, arg);
                warg[u] = fma2(FB[u], Gb, arg);
            }
            s0p = s0c; s1p = s1c; p0p = p0c; p1p = p1c;
        }
#pragma unroll
        for (int u = 0; u < IPT; u++) {         // retire last iteration
            float a0, a1, w0, w1;
            unpack2(warg[u], a0, a1);
            asm("ex2.approx.ftz.f32 %0, %1;" : "=f"(w0) : "f"(a0));
            asm("ex2.approx.ftz.f32 %0, %1;" : "=f"(w1) : "f"(a1));
            float c0 = fmaf(si[u], p0p, s0p);
            float c1 = fmaf(si[u], p1p, s1p);
            acc0[u] = fmaf(w0, c0, acc0[u]);
            acc1[u] = fmaf(w1, c1, acc1[u]);
        }
    }

    float tot = 0.0f;
    if (bi == bj) {
#pragma unroll
        for (int u = 0; u < IPT; u++) tot = fmaf(si[u], acc0[u] + acc1[u], tot);
    } else {
#pragma unroll
        for (int u = 0; u < IPT; u++) tot += acc0[u] + acc1[u];
    }
    tot *= (1.0f / (float)NN);

    // Block reduce: warp shuffle then smem (TPB = 64 -> 2 warps)
#pragma unroll
    for (int off = 16; off > 0; off >>= 1)
        tot += __shfl_xor_sync(0xFFFFFFFFu, tot, off);
    if ((t & 31) == 0) sred[t >> 5] = tot;
    __syncthreads();
    if (t == 0) atomicAdd(out, sred[0] + sred[1]);
}

extern "C" void kernel_launch(void* const* d_in, const int* in_sizes, int n_in,
                              void* d_out, int out_size) {
    const float* inp = (const float*)d_in[0];   // [1,1,96,96] seg probs
    const float* img = (const float*)d_in[1];   // [1,3,96,96] rgb
    float* out = (float*)d_out;

    precompute_kernel<<<(NN / 2 + 255) / 256, 256>>>(inp, img, out, out_size);
    crf_main_kernel<<<NBLOCKS, TPB>>>(out);
}